// round 7
// baseline (speedup 1.0000x reference)
#include <cuda_runtime.h>
#include <cuda_bf16.h>
#include <math.h>
#include <stdint.h>

// ---------------- problem constants ----------------
#define NN      30000
#define IN_DIM  3000
#define DDIM    512
#define HID     512
#define OUTD    30
#define PREDD   20
#define DEG     10
#define EDGES   (NN*DEG)
#define NEG_SLOPE 0.2f

// ---------------- scratch ----------------
__device__ float g_de [NN*DDIM];
__device__ float g_x1 [NN*HID];
__device__ float g_h1 [NN*HID];
__device__ float g_x3 [NN*HID];
__device__ float g_h3 [NN*HID];
__device__ float g_h4 [NN*DDIM];
__device__ float g_a1s[NN];
__device__ float g_a1d[NN];
__device__ float g_alpha[EDGES];
__device__ float g_W2T[OUTD*HID];        // [30][512]
// tf32-rounded weights (fp32 storage, low 13 mantissa bits zero)
__device__ float g_Wenc_r[IN_DIM*DDIM];  // [K=3000, N=512]
__device__ float g_Wdec_r[DDIM*IN_DIM];  // [K=512,  N=3000]
__device__ float g_W1_r  [DDIM*HID];     // [K=512,  N=512]
__device__ float g_W1T_r [HID*DDIM];     // [K=512,  N=512] = W1^T

// ---------------- tf32 rounding helpers ----------------
__device__ __forceinline__ float round_tf32f(float x) {
    uint32_t u;
    asm("cvt.rna.tf32.f32 %0, %1;" : "=r"(u) : "f"(x));
    return __uint_as_float(u);
}
__device__ __forceinline__ uint32_t f2tf32(float f) {
    uint32_t u;
    asm("cvt.rna.tf32.f32 %0, %1;" : "=r"(u) : "f"(f));
    return u;
}

// =====================================================================
// TF32 tensor-core GEMM (templated): C[M,N] = A[M,K] @ B[K,N] (+bias)
// 128x128 tile, BK=32, 8 warps, warp tile 64x32.
// 3-stage cp.async pipeline, ONE __syncthreads per k-iteration.
// ACVT: 1 = A raw fp32 in gmem -> cvt fragments post-LDS (enc path).
// FLAGS bit0 = ELU on output, bit1 = round output to tf32.
// =====================================================================
#define GA_STRIDE 36
#define GB_STRIDE 136
#define STAGES 3
#define STAGE_FLOATS (128*GA_STRIDE + 32*GB_STRIDE)
#define GSMEM_FLOATS (STAGES*STAGE_FLOATS)
#define GSMEM_BYTES  (GSMEM_FLOATS*4)

__device__ __forceinline__ void cp16(uint32_t dst, const float* src, int sz) {
    asm volatile("cp.async.ca.shared.global [%0], [%1], 16, %2;\n"
                 :: "r"(dst), "l"(src), "r"(sz));
}

template<int ACVT, int FLAGS>
__global__ __launch_bounds__(256, 2) void tf32_gemm_kernel(
    const float* __restrict__ A, const float* __restrict__ B,
    const float* __restrict__ bias, float* __restrict__ C,
    int M, int N, int K)
{
    extern __shared__ float sm[];
    float* As = sm;                       // [STAGES][128][36]
    float* Bs = sm + STAGES * 128 * GA_STRIDE;  // [STAGES][32][136]

    const int tid  = threadIdx.x;
    const int lane = tid & 31;
    const int warp = tid >> 5;
    const int wm   = warp >> 2;      // 0..1
    const int wn   = warp & 3;       // 0..3
    const int row0 = blockIdx.y * 128;
    const int col0 = blockIdx.x * 128;
    const int lr   = lane >> 2;      // 0..7
    const int lc   = lane & 3;       // 0..3

    float acc[4][4][4];
    #pragma unroll
    for (int i = 0; i < 4; i++)
        #pragma unroll
        for (int j = 0; j < 4; j++)
            #pragma unroll
            for (int q = 0; q < 4; q++) acc[i][j][q] = 0.f;

    const int nk = (K + 31) >> 5;

    auto load_tile = [&](int stage, int kt) {
        const int k0 = kt << 5;
        float* Asb = As + stage * 128 * GA_STRIDE;
        float* Bsb = Bs + stage * 32 * GB_STRIDE;
        #pragma unroll
        for (int it = 0; it < 4; it++) {
            int idx = tid + it * 256;
            int r = idx >> 3, c4 = (idx & 7) << 2;
            int gr = row0 + r, gc = k0 + c4;
            uint32_t dst = (uint32_t)__cvta_generic_to_shared(&Asb[r * GA_STRIDE + c4]);
            int sz = (gr < M && gc < K) ? 16 : 0;
            cp16(dst, A + (size_t)gr * K + gc, sz);
        }
        #pragma unroll
        for (int it = 0; it < 4; it++) {
            int idx = tid + it * 256;
            int r = idx >> 5, c4 = (idx & 31) << 2;
            int gr = k0 + r, gc = col0 + c4;
            uint32_t dst = (uint32_t)__cvta_generic_to_shared(&Bsb[r * GB_STRIDE + c4]);
            int sz = (gr < K && gc < N) ? 16 : 0;
            cp16(dst, B + (size_t)gr * N + gc, sz);
        }
    };

    // prologue: 2 prefetches (each its own commit group; empty groups OK)
    load_tile(0, 0);
    asm volatile("cp.async.commit_group;\n");
    if (nk > 1) load_tile(1, 1);
    asm volatile("cp.async.commit_group;\n");

    int stage = 0;
    for (int kt = 0; kt < nk; kt++) {
        // stage kt must be complete; kt+1 may remain in flight
        asm volatile("cp.async.wait_group 1;\n");
        __syncthreads();

        // issue load for kt+2 into the stage last used at kt-1 (all warps done)
        if (kt + 2 < nk) load_tile((stage + 2 >= STAGES) ? stage + 2 - STAGES : stage + 2, kt + 2);
        asm volatile("cp.async.commit_group;\n");

        const float*    Asf = As + stage * 128 * GA_STRIDE;
        const uint32_t* Asb = (const uint32_t*)Asf;
        const uint32_t* Bsb = (const uint32_t*)(Bs + stage * 32 * GB_STRIDE);

        #pragma unroll
        for (int ks = 0; ks < 4; ks++) {
            const int kk = ks << 3;
            uint32_t a[4][4], b[4][2];
            #pragma unroll
            for (int ti = 0; ti < 4; ti++) {
                int rb = wm * 64 + ti * 16 + lr;
                int kc = kk + lc;
                if (ACVT) {
                    a[ti][0] = f2tf32(Asf[rb * GA_STRIDE + kc]);
                    a[ti][1] = f2tf32(Asf[(rb + 8) * GA_STRIDE + kc]);
                    a[ti][2] = f2tf32(Asf[rb * GA_STRIDE + kc + 4]);
                    a[ti][3] = f2tf32(Asf[(rb + 8) * GA_STRIDE + kc + 4]);
                } else {
                    a[ti][0] = Asb[rb * GA_STRIDE + kc];
                    a[ti][1] = Asb[(rb + 8) * GA_STRIDE + kc];
                    a[ti][2] = Asb[rb * GA_STRIDE + kc + 4];
                    a[ti][3] = Asb[(rb + 8) * GA_STRIDE + kc + 4];
                }
            }
            #pragma unroll
            for (int tj = 0; tj < 4; tj++) {
                int cb = wn * 32 + tj * 8 + lr;
                int kr = kk + lc;
                b[tj][0] = Bsb[kr * GB_STRIDE + cb];
                b[tj][1] = Bsb[(kr + 4) * GB_STRIDE + cb];
            }
            #pragma unroll
            for (int ti = 0; ti < 4; ti++)
                #pragma unroll
                for (int tj = 0; tj < 4; tj++) {
                    asm volatile(
                        "mma.sync.aligned.m16n8k8.row.col.f32.tf32.tf32.f32 "
                        "{%0,%1,%2,%3}, {%4,%5,%6,%7}, {%8,%9}, {%0,%1,%2,%3};\n"
                        : "+f"(acc[ti][tj][0]), "+f"(acc[ti][tj][1]),
                          "+f"(acc[ti][tj][2]), "+f"(acc[ti][tj][3])
                        : "r"(a[ti][0]), "r"(a[ti][1]), "r"(a[ti][2]), "r"(a[ti][3]),
                          "r"(b[tj][0]), "r"(b[tj][1]));
                }
        }
        stage = (stage + 1 >= STAGES) ? 0 : stage + 1;
    }

    // epilogue (float2 stores; c is even)
    constexpr bool DO_ELU   = (FLAGS & 1) != 0;
    constexpr bool DO_ROUND = (FLAGS & 2) != 0;
    #pragma unroll
    for (int ti = 0; ti < 4; ti++) {
        int r0 = row0 + wm * 64 + ti * 16 + lr;
        int r1 = r0 + 8;
        #pragma unroll
        for (int tj = 0; tj < 4; tj++) {
            int c = col0 + wn * 32 + tj * 8 + (lc << 1);
            float bv0 = 0.f, bv1 = 0.f;
            if (bias && c + 1 < N) {
                float2 bv = *(const float2*)(bias + c);
                bv0 = bv.x; bv1 = bv.y;
            } else if (bias && c < N) bv0 = bias[c];
            #pragma unroll
            for (int h = 0; h < 2; h++) {
                int r = h ? r1 : r0;
                if (r >= M) continue;
                float v0 = acc[ti][tj][h*2+0] + bv0;
                float v1 = acc[ti][tj][h*2+1] + bv1;
                if (DO_ELU) {
                    v0 = (v0 > 0.f) ? v0 : expm1f(v0);
                    v1 = (v1 > 0.f) ? v1 : expm1f(v1);
                }
                if (DO_ROUND) { v0 = round_tf32f(v0); v1 = round_tf32f(v1); }
                if (c + 1 < N) {
                    float2 st; st.x = v0; st.y = v1;
                    *(float2*)(C + (size_t)r * N + c) = st;
                } else if (c < N) {
                    C[(size_t)r * N + c] = v0;
                }
            }
        }
    }
}

// ---------------- prep kernels ----------------
__global__ void round_tf32_kernel(const float* __restrict__ in,
                                  float* __restrict__ out, int n)
{
    int i = blockIdx.x * 256 + threadIdx.x;
    if (i >= n) return;
    out[i] = round_tf32f(in[i]);
}

__global__ void transpose_round_kernel(const float* __restrict__ in,
                                       float* __restrict__ out, int R, int C)
{
    __shared__ float t[32][33];
    int c = blockIdx.x * 32 + threadIdx.x;
    int r = blockIdx.y * 32 + threadIdx.y;
    if (r < R && c < C) t[threadIdx.y][threadIdx.x] = in[r * C + c];
    __syncthreads();
    int r2 = blockIdx.x * 32 + threadIdx.y;
    int c2 = blockIdx.y * 32 + threadIdx.x;
    if (r2 < C && c2 < R) out[r2 * R + c2] = round_tf32f(t[threadIdx.x][threadIdx.y]);
}

__global__ void transpose_kernel(const float* __restrict__ in,
                                 float* __restrict__ out, int R, int C)
{
    __shared__ float t[32][33];
    int c = blockIdx.x * 32 + threadIdx.x;
    int r = blockIdx.y * 32 + threadIdx.y;
    if (r < R && c < C) t[threadIdx.y][threadIdx.x] = in[r * C + c];
    __syncthreads();
    int r2 = blockIdx.x * 32 + threadIdx.y;
    int c2 = blockIdx.y * 32 + threadIdx.x;
    if (r2 < C && c2 < R) out[r2 * R + c2] = t[threadIdx.x][threadIdx.y];
}

// ---------------- h2 = h1 @ W2 (N=30), warp-per-row, W2T in smem ----------
#define W2T_SMEM (OUTD*HID*4)
__global__ __launch_bounds__(256) void h2_kernel(
    const float* __restrict__ h1, const float* __restrict__ W2T,
    float* __restrict__ h2)
{
    extern __shared__ float w[];          // [30][512]
    const int tid = threadIdx.x;
    for (int i = tid; i < OUTD * HID; i += 256) w[i] = W2T[i];
    __syncthreads();
    const int wid = tid >> 5, lane = tid & 31;
    const int row = blockIdx.x * 8 + wid;
    if (row >= NN) return;
    float h[16];
    const float* hr = h1 + (size_t)row * HID;
    #pragma unroll
    for (int j = 0; j < 16; j++) h[j] = hr[lane + 32 * j];
    #pragma unroll
    for (int c = 0; c < OUTD; c++) {
        float s = 0.f;
        const float* wc = w + c * HID;
        #pragma unroll
        for (int j = 0; j < 16; j++) s += h[j] * wc[lane + 32 * j];
        #pragma unroll
        for (int o = 16; o > 0; o >>= 1) s += __shfl_xor_sync(0xffffffffu, s, o);
        if (lane == c) h2[(size_t)row * OUTD + c] = s;   // c<30<32
    }
}

// ---------------- x3 = h2 @ W2^T (K=30), warp-per-row, W2T in smem --------
__global__ __launch_bounds__(256) void x3_kernel(
    const float* __restrict__ h2, const float* __restrict__ W2T,
    float* __restrict__ x3)
{
    extern __shared__ float w[];          // [30][512]
    const int tid = threadIdx.x;
    for (int i = tid; i < OUTD * HID; i += 256) w[i] = W2T[i];
    __syncthreads();
    const int wid = tid >> 5, lane = tid & 31;
    const int row = blockIdx.x * 8 + wid;
    if (row >= NN) return;
    float hc = (lane < OUTD) ? h2[(size_t)row * OUTD + lane] : 0.f;
    float acc[16];
    #pragma unroll
    for (int j = 0; j < 16; j++) acc[j] = 0.f;
    #pragma unroll
    for (int c = 0; c < OUTD; c++) {
        float b = __shfl_sync(0xffffffffu, hc, c);
        const float* wc = w + c * HID;
        #pragma unroll
        for (int j = 0; j < 16; j++) acc[j] += b * wc[lane + 32 * j];
    }
    float* xr = x3 + (size_t)row * HID;
    #pragma unroll
    for (int j = 0; j < 16; j++) xr[lane + 32 * j] = acc[j];
}

// ---------------- attention logits ----------------
__global__ void row_logits_kernel(const float* __restrict__ x1,
                                  const float* __restrict__ att_s,
                                  const float* __restrict__ att_d,
                                  float* __restrict__ a1s,
                                  float* __restrict__ a1d, int n)
{
    int row = blockIdx.x * 8 + threadIdx.y;
    if (row >= n) return;
    int lane = threadIdx.x;
    float s = 0.f, d = 0.f;
    const float* xr = x1 + (size_t)row * HID;
    #pragma unroll 4
    for (int k = lane; k < HID; k += 32) {
        float v = xr[k];
        s += v * att_s[k];
        d += v * att_d[k];
    }
    #pragma unroll
    for (int o = 16; o > 0; o >>= 1) {
        s += __shfl_down_sync(0xffffffffu, s, o);
        d += __shfl_down_sync(0xffffffffu, d, o);
    }
    if (lane == 0) { a1s[row] = s; a1d[row] = d; }
}

// ---------------- edge softmax ----------------
__global__ void alpha_kernel(const int* __restrict__ src,
                             const int* __restrict__ dst,
                             const float* __restrict__ a1s,
                             const float* __restrict__ a1d,
                             float* __restrict__ alpha, int n)
{
    int i = blockIdx.x * 256 + threadIdx.x;
    if (i >= n) return;
    float e[DEG];
    float m = -1e30f;
    #pragma unroll
    for (int j = 0; j < DEG; j++) {
        int eidx = i * DEG + j;
        float v = a1s[src[eidx]] + a1d[dst[eidx]];
        v = (v > 0.f) ? v : NEG_SLOPE * v;
        e[j] = v;
        m = fmaxf(m, v);
    }
    float sum = 0.f;
    #pragma unroll
    for (int j = 0; j < DEG; j++) { e[j] = __expf(e[j] - m); sum += e[j]; }
    float inv = 1.f / sum;
    #pragma unroll
    for (int j = 0; j < DEG; j++) alpha[i * DEG + j] = e[j] * inv;
}

// ---------------- weighted aggregation + ELU (+opt round) ----------------
__global__ __launch_bounds__(128) void agg_elu_kernel(
    const float* __restrict__ x, const int* __restrict__ src,
    const float* __restrict__ alpha, float* __restrict__ out, int round_out)
{
    int i = blockIdx.x;
    __shared__ int   ss[DEG];
    __shared__ float sa[DEG];
    if (threadIdx.x < DEG) {
        ss[threadIdx.x] = src[i * DEG + threadIdx.x];
        sa[threadIdx.x] = alpha[i * DEG + threadIdx.x];
    }
    __syncthreads();
    int c0 = threadIdx.x * 4;
    float a0 = 0.f, a1 = 0.f, a2 = 0.f, a3 = 0.f;
    #pragma unroll
    for (int j = 0; j < DEG; j++) {
        const float4 v = *(const float4*)&x[(size_t)ss[j] * HID + c0];
        float a = sa[j];
        a0 += a * v.x; a1 += a * v.y; a2 += a * v.z; a3 += a * v.w;
    }
    float4 r;
    r.x = (a0 > 0.f) ? a0 : expm1f(a0);
    r.y = (a1 > 0.f) ? a1 : expm1f(a1);
    r.z = (a2 > 0.f) ? a2 : expm1f(a2);
    r.w = (a3 > 0.f) ? a3 : expm1f(a3);
    if (round_out) {
        r.x = round_tf32f(r.x); r.y = round_tf32f(r.y);
        r.z = round_tf32f(r.z); r.w = round_tf32f(r.w);
    }
    *(float4*)&out[(size_t)i * HID + c0] = r;
}

// ---------------- prediction head ----------------
__global__ void pred_kernel(const float* __restrict__ h2,
                            const float* __restrict__ Wp,
                            const float* __restrict__ bp,
                            float* __restrict__ logp, int n)
{
    int i = blockIdx.x * 128 + threadIdx.x;
    if (i >= n) return;
    float h[OUTD];
    #pragma unroll
    for (int k = 0; k < OUTD; k++) h[k] = h2[(size_t)i * OUTD + k];
    float p[PREDD];
    float m = -1e30f;
    #pragma unroll
    for (int c = 0; c < PREDD; c++) {
        float s = bp[c];
        #pragma unroll
        for (int k = 0; k < OUTD; k++) s += h[k] * Wp[k * PREDD + c];
        p[c] = s;
        m = fmaxf(m, s);
    }
    float sum = 0.f;
    #pragma unroll
    for (int c = 0; c < PREDD; c++) sum += expf(p[c] - m);
    float lse = m + logf(sum);
    #pragma unroll
    for (int c = 0; c < PREDD; c++) logp[(size_t)i * PREDD + c] = p[c] - lse;
}

// ---------------- launch ----------------
static inline dim3 tf32_grid(int M, int N) {
    return dim3((N + 127) / 128, (M + 127) / 128);
}

extern "C" void kernel_launch(void* const* d_in, const int* in_sizes, int n_in,
                              void* d_out, int out_size)
{
    const float* features = (const float*)d_in[0];
    const int*   edge     = (const int*)  d_in[1];
    const float* W_enc    = (const float*)d_in[2];
    const float* b_enc    = (const float*)d_in[3];
    const float* W1       = (const float*)d_in[4];
    const float* att_src  = (const float*)d_in[5];
    const float* att_dst  = (const float*)d_in[6];
    const float* W2       = (const float*)d_in[7];
    const float* W_pred   = (const float*)d_in[8];
    const float* b_pred   = (const float*)d_in[9];
    const float* W_dec    = (const float*)d_in[10];
    const float* b_dec    = (const float*)d_in[11];

    const int* src = edge;
    const int* dst = edge + EDGES;

    float* out  = (float*)d_out;
    float* h2   = out;
    float* outm = out + (size_t)NN * OUTD;
    float* logp = out + (size_t)NN * OUTD + (size_t)NN * IN_DIM;

    float *de, *x1, *h1, *x3, *h3, *h4, *a1s, *a1d, *alpha, *W2T;
    float *Wenc_r, *Wdec_r, *W1_r, *W1T_r;
    cudaGetSymbolAddress((void**)&de,    g_de);
    cudaGetSymbolAddress((void**)&x1,    g_x1);
    cudaGetSymbolAddress((void**)&h1,    g_h1);
    cudaGetSymbolAddress((void**)&x3,    g_x3);
    cudaGetSymbolAddress((void**)&h3,    g_h3);
    cudaGetSymbolAddress((void**)&h4,    g_h4);
    cudaGetSymbolAddress((void**)&a1s,   g_a1s);
    cudaGetSymbolAddress((void**)&a1d,   g_a1d);
    cudaGetSymbolAddress((void**)&alpha, g_alpha);
    cudaGetSymbolAddress((void**)&W2T,   g_W2T);
    cudaGetSymbolAddress((void**)&Wenc_r, g_Wenc_r);
    cudaGetSymbolAddress((void**)&Wdec_r, g_Wdec_r);
    cudaGetSymbolAddress((void**)&W1_r,   g_W1_r);
    cudaGetSymbolAddress((void**)&W1T_r,  g_W1T_r);

    static int attr_set = 0;
    if (!attr_set) {
        cudaFuncSetAttribute(tf32_gemm_kernel<1,2>,
            cudaFuncAttributeMaxDynamicSharedMemorySize, GSMEM_BYTES);
        cudaFuncSetAttribute(tf32_gemm_kernel<0,0>,
            cudaFuncAttributeMaxDynamicSharedMemorySize, GSMEM_BYTES);
        cudaFuncSetAttribute(tf32_gemm_kernel<0,3>,
            cudaFuncAttributeMaxDynamicSharedMemorySize, GSMEM_BYTES);
        cudaFuncSetAttribute(h2_kernel,
            cudaFuncAttributeMaxDynamicSharedMemorySize, W2T_SMEM);
        cudaFuncSetAttribute(x3_kernel,
            cudaFuncAttributeMaxDynamicSharedMemorySize, W2T_SMEM);
        attr_set = 1;
    }

    // ---- weight prep (tiny) ----
    round_tf32_kernel<<<(IN_DIM*DDIM + 255)/256, 256>>>(W_enc, Wenc_r, IN_DIM*DDIM);
    round_tf32_kernel<<<(DDIM*IN_DIM + 255)/256, 256>>>(W_dec, Wdec_r, DDIM*IN_DIM);
    round_tf32_kernel<<<(DDIM*HID + 255)/256, 256>>>(W1, W1_r, DDIM*HID);
    transpose_round_kernel<<<dim3((HID + 31)/32, (DDIM + 31)/32), dim3(32, 32)>>>(W1, W1T_r, DDIM, HID);
    transpose_kernel<<<dim3((OUTD + 31)/32, (HID + 31)/32), dim3(32, 32)>>>(W2, W2T, HID, OUTD);

    // 1. de = round_tf32(features @ W_enc + b_enc)   [30000,512] K=3000
    tf32_gemm_kernel<1,2><<<tf32_grid(NN, DDIM), 256, GSMEM_BYTES>>>(
        features, Wenc_r, b_enc, de, NN, DDIM, IN_DIM);
    // 2. x1 = de @ W1                                [30000,512] K=512
    tf32_gemm_kernel<0,0><<<tf32_grid(NN, HID), 256, GSMEM_BYTES>>>(
        de, W1_r, nullptr, x1, NN, HID, DDIM);
    // 3. attention logits
    row_logits_kernel<<<(NN + 7)/8, dim3(32, 8)>>>(x1, att_src, att_dst, a1s, a1d, NN);
    // 4. edge softmax
    alpha_kernel<<<(NN + 255)/256, 256>>>(src, dst, a1s, a1d, alpha, NN);
    // 5. h1 = elu(agg(x1))
    agg_elu_kernel<<<NN, 128>>>(x1, src, alpha, h1, 0);
    // 6. h2 = h1 @ W2  (output 0)
    h2_kernel<<<(NN + 7)/8, 256, W2T_SMEM>>>(h1, W2T, h2);
    // 7. log-softmax head (output 2)
    pred_kernel<<<(NN + 127)/128, 128>>>(h2, W_pred, b_pred, logp, NN);
    // 8. x3 = h2 @ W2^T
    x3_kernel<<<(NN + 7)/8, 256, W2T_SMEM>>>(h2, W2T, x3);
    // 9. h3 = round_tf32(elu(agg(x3)))
    agg_elu_kernel<<<NN, 128>>>(x3, src, alpha, h3, 1);
    // 10. h4 = round_tf32(elu(h3 @ W1^T))            [30000,512] K=512
    tf32_gemm_kernel<0,3><<<tf32_grid(NN, DDIM), 256, GSMEM_BYTES>>>(
        h3, W1T_r, nullptr, h4, NN, DDIM, HID);
    // 11. out = h4 @ W_dec + b_dec                   [30000,3000] K=512 (output 1)
    tf32_gemm_kernel<0,0><<<tf32_grid(NN, IN_DIM), 256, GSMEM_BYTES>>>(
        h4, Wdec_r, b_dec, outm, NN, IN_DIM, DDIM);
}

// round 8
// speedup vs baseline: 1.1945x; 1.1945x over previous
#include <cuda_runtime.h>
#include <cuda_bf16.h>
#include <math.h>
#include <stdint.h>

// ---------------- problem constants ----------------
#define NN      30000
#define IN_DIM  3000
#define DDIM    512
#define HID     512
#define OUTD    30
#define PREDD   20
#define DEG     10
#define EDGES   (NN*DEG)
#define NEG_SLOPE 0.2f

// ---------------- scratch ----------------
__device__ float g_de [NN*DDIM];
__device__ float g_x1 [NN*HID];
__device__ float g_h1 [NN*HID];
__device__ float g_x3 [NN*HID];
__device__ float g_h3 [NN*HID];
__device__ float g_h4 [NN*DDIM];
__device__ float g_a1s[NN];
__device__ float g_a1d[NN];
__device__ float g_alpha[EDGES];
__device__ float g_W2T[OUTD*HID];        // [30][512]
// tf32-rounded weights (fp32 storage, low 13 mantissa bits zero)
__device__ float g_Wenc_r[IN_DIM*DDIM];  // [K=3000, N=512]
__device__ float g_Wdec_r[DDIM*IN_DIM];  // [K=512,  N=3000]
__device__ float g_W1_r  [DDIM*HID];     // [K=512,  N=512]
__device__ float g_W1T_r [HID*DDIM];     // [K=512,  N=512] = W1^T

// ---------------- tf32 rounding helpers ----------------
__device__ __forceinline__ float round_tf32f(float x) {
    uint32_t u;
    asm("cvt.rna.tf32.f32 %0, %1;" : "=r"(u) : "f"(x));
    return __uint_as_float(u);
}
__device__ __forceinline__ uint32_t f2tf32(float f) {
    uint32_t u;
    asm("cvt.rna.tf32.f32 %0, %1;" : "=r"(u) : "f"(f));
    return u;
}

// =====================================================================
// TF32 tensor-core GEMM (templated): C[M,N] = A[M,K] @ B[K,N] (+bias)
// 128x128 tile, BK=32, 8 warps, warp tile 64x32.
// 3-stage cp.async.CG pipeline (L2-only; no L1 pollution),
// ONE __syncthreads per k-iteration.
// ACVT: 1 = A raw fp32 in gmem -> cvt fragments post-LDS (enc path).
// FLAGS bit0 = ELU on output, bit1 = round output to tf32.
// =====================================================================
#define GA_STRIDE 36
#define GB_STRIDE 136
#define STAGES 3
#define STAGE_FLOATS (128*GA_STRIDE + 32*GB_STRIDE)
#define GSMEM_FLOATS (STAGES*STAGE_FLOATS)
#define GSMEM_BYTES  (GSMEM_FLOATS*4)

__device__ __forceinline__ void cp16cg(uint32_t dst, const float* src, int sz) {
    asm volatile("cp.async.cg.shared.global [%0], [%1], 16, %2;\n"
                 :: "r"(dst), "l"(src), "r"(sz));
}

template<int ACVT, int FLAGS>
__global__ __launch_bounds__(256, 2) void tf32_gemm_kernel(
    const float* __restrict__ A, const float* __restrict__ B,
    const float* __restrict__ bias, float* __restrict__ C,
    int M, int N, int K)
{
    extern __shared__ float sm[];
    float* As = sm;                             // [STAGES][128][36]
    float* Bs = sm + STAGES * 128 * GA_STRIDE;  // [STAGES][32][136]

    const int tid  = threadIdx.x;
    const int lane = tid & 31;
    const int warp = tid >> 5;
    const int wm   = warp >> 2;      // 0..1
    const int wn   = warp & 3;       // 0..3
    const int row0 = blockIdx.y * 128;
    const int col0 = blockIdx.x * 128;
    const int lr   = lane >> 2;      // 0..7
    const int lc   = lane & 3;       // 0..3

    float acc[4][4][4];
    #pragma unroll
    for (int i = 0; i < 4; i++)
        #pragma unroll
        for (int j = 0; j < 4; j++)
            #pragma unroll
            for (int q = 0; q < 4; q++) acc[i][j][q] = 0.f;

    const int nk = (K + 31) >> 5;

    auto load_tile = [&](int stage, int kt) {
        const int k0 = kt << 5;
        float* Asb = As + stage * 128 * GA_STRIDE;
        float* Bsb = Bs + stage * 32 * GB_STRIDE;
        #pragma unroll
        for (int it = 0; it < 4; it++) {
            int idx = tid + it * 256;
            int r = idx >> 3, c4 = (idx & 7) << 2;
            int gr = row0 + r, gc = k0 + c4;
            uint32_t dst = (uint32_t)__cvta_generic_to_shared(&Asb[r * GA_STRIDE + c4]);
            int sz = (gr < M && gc < K) ? 16 : 0;
            cp16cg(dst, A + (size_t)gr * K + gc, sz);
        }
        #pragma unroll
        for (int it = 0; it < 4; it++) {
            int idx = tid + it * 256;
            int r = idx >> 5, c4 = (idx & 31) << 2;
            int gr = k0 + r, gc = col0 + c4;
            uint32_t dst = (uint32_t)__cvta_generic_to_shared(&Bsb[r * GB_STRIDE + c4]);
            int sz = (gr < K && gc < N) ? 16 : 0;
            cp16cg(dst, B + (size_t)gr * N + gc, sz);
        }
    };

    // prologue: 2 prefetches
    load_tile(0, 0);
    asm volatile("cp.async.commit_group;\n");
    if (nk > 1) load_tile(1, 1);
    asm volatile("cp.async.commit_group;\n");

    int stage = 0;
    for (int kt = 0; kt < nk; kt++) {
        asm volatile("cp.async.wait_group 1;\n");
        __syncthreads();

        if (kt + 2 < nk) load_tile((stage + 2 >= STAGES) ? stage + 2 - STAGES : stage + 2, kt + 2);
        asm volatile("cp.async.commit_group;\n");

        const float*    Asf = As + stage * 128 * GA_STRIDE;
        const uint32_t* Asb = (const uint32_t*)Asf;
        const uint32_t* Bsb = (const uint32_t*)(Bs + stage * 32 * GB_STRIDE);

        #pragma unroll
        for (int ks = 0; ks < 4; ks++) {
            const int kk = ks << 3;
            uint32_t a[4][4], b[4][2];
            #pragma unroll
            for (int ti = 0; ti < 4; ti++) {
                int rb = wm * 64 + ti * 16 + lr;
                int kc = kk + lc;
                if (ACVT) {
                    a[ti][0] = f2tf32(Asf[rb * GA_STRIDE + kc]);
                    a[ti][1] = f2tf32(Asf[(rb + 8) * GA_STRIDE + kc]);
                    a[ti][2] = f2tf32(Asf[rb * GA_STRIDE + kc + 4]);
                    a[ti][3] = f2tf32(Asf[(rb + 8) * GA_STRIDE + kc + 4]);
                } else {
                    a[ti][0] = Asb[rb * GA_STRIDE + kc];
                    a[ti][1] = Asb[(rb + 8) * GA_STRIDE + kc];
                    a[ti][2] = Asb[rb * GA_STRIDE + kc + 4];
                    a[ti][3] = Asb[(rb + 8) * GA_STRIDE + kc + 4];
                }
            }
            #pragma unroll
            for (int tj = 0; tj < 4; tj++) {
                int cb = wn * 32 + tj * 8 + lr;
                int kr = kk + lc;
                b[tj][0] = Bsb[kr * GB_STRIDE + cb];
                b[tj][1] = Bsb[(kr + 4) * GB_STRIDE + cb];
            }
            #pragma unroll
            for (int ti = 0; ti < 4; ti++)
                #pragma unroll
                for (int tj = 0; tj < 4; tj++) {
                    asm volatile(
                        "mma.sync.aligned.m16n8k8.row.col.f32.tf32.tf32.f32 "
                        "{%0,%1,%2,%3}, {%4,%5,%6,%7}, {%8,%9}, {%0,%1,%2,%3};\n"
                        : "+f"(acc[ti][tj][0]), "+f"(acc[ti][tj][1]),
                          "+f"(acc[ti][tj][2]), "+f"(acc[ti][tj][3])
                        : "r"(a[ti][0]), "r"(a[ti][1]), "r"(a[ti][2]), "r"(a[ti][3]),
                          "r"(b[tj][0]), "r"(b[tj][1]));
                }
        }
        stage = (stage + 1 >= STAGES) ? 0 : stage + 1;
    }

    // epilogue (float2 stores; c is even)
    constexpr bool DO_ELU   = (FLAGS & 1) != 0;
    constexpr bool DO_ROUND = (FLAGS & 2) != 0;
    #pragma unroll
    for (int ti = 0; ti < 4; ti++) {
        int r0 = row0 + wm * 64 + ti * 16 + lr;
        int r1 = r0 + 8;
        #pragma unroll
        for (int tj = 0; tj < 4; tj++) {
            int c = col0 + wn * 32 + tj * 8 + (lc << 1);
            float bv0 = 0.f, bv1 = 0.f;
            if (bias && c + 1 < N) {
                float2 bv = *(const float2*)(bias + c);
                bv0 = bv.x; bv1 = bv.y;
            } else if (bias && c < N) bv0 = bias[c];
            #pragma unroll
            for (int h = 0; h < 2; h++) {
                int r = h ? r1 : r0;
                if (r >= M) continue;
                float v0 = acc[ti][tj][h*2+0] + bv0;
                float v1 = acc[ti][tj][h*2+1] + bv1;
                if (DO_ELU) {
                    v0 = (v0 > 0.f) ? v0 : expm1f(v0);
                    v1 = (v1 > 0.f) ? v1 : expm1f(v1);
                }
                if (DO_ROUND) { v0 = round_tf32f(v0); v1 = round_tf32f(v1); }
                if (c + 1 < N) {
                    float2 st; st.x = v0; st.y = v1;
                    *(float2*)(C + (size_t)r * N + c) = st;
                } else if (c < N) {
                    C[(size_t)r * N + c] = v0;
                }
            }
        }
    }
}

// ---------------- prep kernels ----------------
__global__ void round_tf32_kernel(const float* __restrict__ in,
                                  float* __restrict__ out, int n)
{
    int i = blockIdx.x * 256 + threadIdx.x;
    if (i >= n) return;
    out[i] = round_tf32f(in[i]);
}

__global__ void transpose_round_kernel(const float* __restrict__ in,
                                       float* __restrict__ out, int R, int C)
{
    __shared__ float t[32][33];
    int c = blockIdx.x * 32 + threadIdx.x;
    int r = blockIdx.y * 32 + threadIdx.y;
    if (r < R && c < C) t[threadIdx.y][threadIdx.x] = in[r * C + c];
    __syncthreads();
    int r2 = blockIdx.x * 32 + threadIdx.y;
    int c2 = blockIdx.y * 32 + threadIdx.x;
    if (r2 < C && c2 < R) out[r2 * R + c2] = round_tf32f(t[threadIdx.x][threadIdx.y]);
}

__global__ void transpose_kernel(const float* __restrict__ in,
                                 float* __restrict__ out, int R, int C)
{
    __shared__ float t[32][33];
    int c = blockIdx.x * 32 + threadIdx.x;
    int r = blockIdx.y * 32 + threadIdx.y;
    if (r < R && c < C) t[threadIdx.y][threadIdx.x] = in[r * C + c];
    __syncthreads();
    int r2 = blockIdx.x * 32 + threadIdx.y;
    int c2 = blockIdx.y * 32 + threadIdx.x;
    if (r2 < C && c2 < R) out[r2 * R + c2] = t[threadIdx.x][threadIdx.y];
}

// ---------------- h2 = h1 @ W2 (N=30), warp-per-row, W2T in smem ----------
#define W2T_SMEM (OUTD*HID*4)
__global__ __launch_bounds__(256) void h2_kernel(
    const float* __restrict__ h1, const float* __restrict__ W2T,
    float* __restrict__ h2)
{
    extern __shared__ float w[];          // [30][512]
    const int tid = threadIdx.x;
    for (int i = tid; i < OUTD * HID; i += 256) w[i] = W2T[i];
    __syncthreads();
    const int wid = tid >> 5, lane = tid & 31;
    const int row = blockIdx.x * 8 + wid;
    if (row >= NN) return;
    float h[16];
    const float* hr = h1 + (size_t)row * HID;
    #pragma unroll
    for (int j = 0; j < 16; j++) h[j] = hr[lane + 32 * j];
    #pragma unroll
    for (int c = 0; c < OUTD; c++) {
        float s = 0.f;
        const float* wc = w + c * HID;
        #pragma unroll
        for (int j = 0; j < 16; j++) s += h[j] * wc[lane + 32 * j];
        #pragma unroll
        for (int o = 16; o > 0; o >>= 1) s += __shfl_xor_sync(0xffffffffu, s, o);
        if (lane == c) h2[(size_t)row * OUTD + c] = s;   // c<30<32
    }
}

// ---------------- x3 = h2 @ W2^T (K=30), warp-per-row, W2T in smem --------
__global__ __launch_bounds__(256) void x3_kernel(
    const float* __restrict__ h2, const float* __restrict__ W2T,
    float* __restrict__ x3)
{
    extern __shared__ float w[];          // [30][512]
    const int tid = threadIdx.x;
    for (int i = tid; i < OUTD * HID; i += 256) w[i] = W2T[i];
    __syncthreads();
    const int wid = tid >> 5, lane = tid & 31;
    const int row = blockIdx.x * 8 + wid;
    if (row >= NN) return;
    float hc = (lane < OUTD) ? h2[(size_t)row * OUTD + lane] : 0.f;
    float acc[16];
    #pragma unroll
    for (int j = 0; j < 16; j++) acc[j] = 0.f;
    #pragma unroll
    for (int c = 0; c < OUTD; c++) {
        float b = __shfl_sync(0xffffffffu, hc, c);
        const float* wc = w + c * HID;
        #pragma unroll
        for (int j = 0; j < 16; j++) acc[j] += b * wc[lane + 32 * j];
    }
    float* xr = x3 + (size_t)row * HID;
    #pragma unroll
    for (int j = 0; j < 16; j++) xr[lane + 32 * j] = acc[j];
}

// ---------------- attention logits ----------------
__global__ void row_logits_kernel(const float* __restrict__ x1,
                                  const float* __restrict__ att_s,
                                  const float* __restrict__ att_d,
                                  float* __restrict__ a1s,
                                  float* __restrict__ a1d, int n)
{
    int row = blockIdx.x * 8 + threadIdx.y;
    if (row >= n) return;
    int lane = threadIdx.x;
    float s = 0.f, d = 0.f;
    const float* xr = x1 + (size_t)row * HID;
    #pragma unroll 4
    for (int k = lane; k < HID; k += 32) {
        float v = xr[k];
        s += v * att_s[k];
        d += v * att_d[k];
    }
    #pragma unroll
    for (int o = 16; o > 0; o >>= 1) {
        s += __shfl_down_sync(0xffffffffu, s, o);
        d += __shfl_down_sync(0xffffffffu, d, o);
    }
    if (lane == 0) { a1s[row] = s; a1d[row] = d; }
}

// ---------------- edge softmax ----------------
__global__ void alpha_kernel(const int* __restrict__ src,
                             const int* __restrict__ dst,
                             const float* __restrict__ a1s,
                             const float* __restrict__ a1d,
                             float* __restrict__ alpha, int n)
{
    int i = blockIdx.x * 256 + threadIdx.x;
    if (i >= n) return;
    float e[DEG];
    float m = -1e30f;
    #pragma unroll
    for (int j = 0; j < DEG; j++) {
        int eidx = i * DEG + j;
        float v = a1s[src[eidx]] + a1d[dst[eidx]];
        v = (v > 0.f) ? v : NEG_SLOPE * v;
        e[j] = v;
        m = fmaxf(m, v);
    }
    float sum = 0.f;
    #pragma unroll
    for (int j = 0; j < DEG; j++) { e[j] = __expf(e[j] - m); sum += e[j]; }
    float inv = 1.f / sum;
    #pragma unroll
    for (int j = 0; j < DEG; j++) alpha[i * DEG + j] = e[j] * inv;
}

// ---------------- weighted aggregation + ELU (+opt round) ----------------
__global__ __launch_bounds__(128) void agg_elu_kernel(
    const float* __restrict__ x, const int* __restrict__ src,
    const float* __restrict__ alpha, float* __restrict__ out, int round_out)
{
    int i = blockIdx.x;
    __shared__ int   ss[DEG];
    __shared__ float sa[DEG];
    if (threadIdx.x < DEG) {
        ss[threadIdx.x] = src[i * DEG + threadIdx.x];
        sa[threadIdx.x] = alpha[i * DEG + threadIdx.x];
    }
    __syncthreads();
    int c0 = threadIdx.x * 4;
    float a0 = 0.f, a1 = 0.f, a2 = 0.f, a3 = 0.f;
    #pragma unroll
    for (int j = 0; j < DEG; j++) {
        const float4 v = *(const float4*)&x[(size_t)ss[j] * HID + c0];
        float a = sa[j];
        a0 += a * v.x; a1 += a * v.y; a2 += a * v.z; a3 += a * v.w;
    }
    float4 r;
    r.x = (a0 > 0.f) ? a0 : expm1f(a0);
    r.y = (a1 > 0.f) ? a1 : expm1f(a1);
    r.z = (a2 > 0.f) ? a2 : expm1f(a2);
    r.w = (a3 > 0.f) ? a3 : expm1f(a3);
    if (round_out) {
        r.x = round_tf32f(r.x); r.y = round_tf32f(r.y);
        r.z = round_tf32f(r.z); r.w = round_tf32f(r.w);
    }
    *(float4*)&out[(size_t)i * HID + c0] = r;
}

// ---------------- prediction head ----------------
__global__ void pred_kernel(const float* __restrict__ h2,
                            const float* __restrict__ Wp,
                            const float* __restrict__ bp,
                            float* __restrict__ logp, int n)
{
    int i = blockIdx.x * 128 + threadIdx.x;
    if (i >= n) return;
    float h[OUTD];
    #pragma unroll
    for (int k = 0; k < OUTD; k++) h[k] = h2[(size_t)i * OUTD + k];
    float p[PREDD];
    float m = -1e30f;
    #pragma unroll
    for (int c = 0; c < PREDD; c++) {
        float s = bp[c];
        #pragma unroll
        for (int k = 0; k < OUTD; k++) s += h[k] * Wp[k * PREDD + c];
        p[c] = s;
        m = fmaxf(m, s);
    }
    float sum = 0.f;
    #pragma unroll
    for (int c = 0; c < PREDD; c++) sum += expf(p[c] - m);
    float lse = m + logf(sum);
    #pragma unroll
    for (int c = 0; c < PREDD; c++) logp[(size_t)i * PREDD + c] = p[c] - lse;
}

// ---------------- launch ----------------
static inline dim3 tf32_grid(int M, int N) {
    return dim3((N + 127) / 128, (M + 127) / 128);
}

extern "C" void kernel_launch(void* const* d_in, const int* in_sizes, int n_in,
                              void* d_out, int out_size)
{
    const float* features = (const float*)d_in[0];
    const int*   edge     = (const int*)  d_in[1];
    const float* W_enc    = (const float*)d_in[2];
    const float* b_enc    = (const float*)d_in[3];
    const float* W1       = (const float*)d_in[4];
    const float* att_src  = (const float*)d_in[5];
    const float* att_dst  = (const float*)d_in[6];
    const float* W2       = (const float*)d_in[7];
    const float* W_pred   = (const float*)d_in[8];
    const float* b_pred   = (const float*)d_in[9];
    const float* W_dec    = (const float*)d_in[10];
    const float* b_dec    = (const float*)d_in[11];

    const int* src = edge;
    const int* dst = edge + EDGES;

    float* out  = (float*)d_out;
    float* h2   = out;
    float* outm = out + (size_t)NN * OUTD;
    float* logp = out + (size_t)NN * OUTD + (size_t)NN * IN_DIM;

    float *de, *x1, *h1, *x3, *h3, *h4, *a1s, *a1d, *alpha, *W2T;
    float *Wenc_r, *Wdec_r, *W1_r, *W1T_r;
    cudaGetSymbolAddress((void**)&de,    g_de);
    cudaGetSymbolAddress((void**)&x1,    g_x1);
    cudaGetSymbolAddress((void**)&h1,    g_h1);
    cudaGetSymbolAddress((void**)&x3,    g_x3);
    cudaGetSymbolAddress((void**)&h3,    g_h3);
    cudaGetSymbolAddress((void**)&h4,    g_h4);
    cudaGetSymbolAddress((void**)&a1s,   g_a1s);
    cudaGetSymbolAddress((void**)&a1d,   g_a1d);
    cudaGetSymbolAddress((void**)&alpha, g_alpha);
    cudaGetSymbolAddress((void**)&W2T,   g_W2T);
    cudaGetSymbolAddress((void**)&Wenc_r, g_Wenc_r);
    cudaGetSymbolAddress((void**)&Wdec_r, g_Wdec_r);
    cudaGetSymbolAddress((void**)&W1_r,   g_W1_r);
    cudaGetSymbolAddress((void**)&W1T_r,  g_W1T_r);

    static int attr_set = 0;
    if (!attr_set) {
        cudaFuncSetAttribute(tf32_gemm_kernel<1,2>,
            cudaFuncAttributeMaxDynamicSharedMemorySize, GSMEM_BYTES);
        cudaFuncSetAttribute(tf32_gemm_kernel<0,0>,
            cudaFuncAttributeMaxDynamicSharedMemorySize, GSMEM_BYTES);
        cudaFuncSetAttribute(tf32_gemm_kernel<0,3>,
            cudaFuncAttributeMaxDynamicSharedMemorySize, GSMEM_BYTES);
        cudaFuncSetAttribute(h2_kernel,
            cudaFuncAttributeMaxDynamicSharedMemorySize, W2T_SMEM);
        cudaFuncSetAttribute(x3_kernel,
            cudaFuncAttributeMaxDynamicSharedMemorySize, W2T_SMEM);
        attr_set = 1;
    }

    // ---- weight prep (tiny) ----
    round_tf32_kernel<<<(IN_DIM*DDIM + 255)/256, 256>>>(W_enc, Wenc_r, IN_DIM*DDIM);
    round_tf32_kernel<<<(DDIM*IN_DIM + 255)/256, 256>>>(W_dec, Wdec_r, DDIM*IN_DIM);
    round_tf32_kernel<<<(DDIM*HID + 255)/256, 256>>>(W1, W1_r, DDIM*HID);
    transpose_round_kernel<<<dim3((HID + 31)/32, (DDIM + 31)/32), dim3(32, 32)>>>(W1, W1T_r, DDIM, HID);
    transpose_kernel<<<dim3((OUTD + 31)/32, (HID + 31)/32), dim3(32, 32)>>>(W2, W2T, HID, OUTD);

    // 1. de = round_tf32(features @ W_enc + b_enc)   [30000,512] K=3000
    tf32_gemm_kernel<1,2><<<tf32_grid(NN, DDIM), 256, GSMEM_BYTES>>>(
        features, Wenc_r, b_enc, de, NN, DDIM, IN_DIM);
    // 2. x1 = de @ W1                                [30000,512] K=512
    tf32_gemm_kernel<0,0><<<tf32_grid(NN, HID), 256, GSMEM_BYTES>>>(
        de, W1_r, nullptr, x1, NN, HID, DDIM);
    // 3. attention logits
    row_logits_kernel<<<(NN + 7)/8, dim3(32, 8)>>>(x1, att_src, att_dst, a1s, a1d, NN);
    // 4. edge softmax
    alpha_kernel<<<(NN + 255)/256, 256>>>(src, dst, a1s, a1d, alpha, NN);
    // 5. h1 = elu(agg(x1))
    agg_elu_kernel<<<NN, 128>>>(x1, src, alpha, h1, 0);
    // 6. h2 = h1 @ W2  (output 0)
    h2_kernel<<<(NN + 7)/8, 256, W2T_SMEM>>>(h1, W2T, h2);
    // 7. log-softmax head (output 2)
    pred_kernel<<<(NN + 127)/128, 128>>>(h2, W_pred, b_pred, logp, NN);
    // 8. x3 = h2 @ W2^T
    x3_kernel<<<(NN + 7)/8, 256, W2T_SMEM>>>(h2, W2T, x3);
    // 9. h3 = round_tf32(elu(agg(x3)))
    agg_elu_kernel<<<NN, 128>>>(x3, src, alpha, h3, 1);
    // 10. h4 = round_tf32(elu(h3 @ W1^T))            [30000,512] K=512
    tf32_gemm_kernel<0,3><<<tf32_grid(NN, DDIM), 256, GSMEM_BYTES>>>(
        h3, W1T_r, nullptr, h4, NN, DDIM, HID);
    // 11. out = h4 @ W_dec + b_dec                   [30000,3000] K=512 (output 1)
    tf32_gemm_kernel<0,0><<<tf32_grid(NN, IN_DIM), 256, GSMEM_BYTES>>>(
        h4, Wdec_r, b_dec, outm, NN, IN_DIM, DDIM);
}

// round 9
// speedup vs baseline: 1.2850x; 1.0757x over previous
#include <cuda_runtime.h>
#include <cuda_bf16.h>
#include <math.h>
#include <stdint.h>

// ---------------- problem constants ----------------
#define NN      30000
#define IN_DIM  3000
#define DDIM    512
#define HID     512
#define OUTD    30
#define PREDD   20
#define DEG     10
#define EDGES   (NN*DEG)
#define NEG_SLOPE 0.2f

// ---------------- scratch ----------------
__device__ float g_x1 [NN*HID];
__device__ float g_h1 [NN*HID];
__device__ float g_x3 [NN*HID];
__device__ float g_h3 [NN*HID];
__device__ float g_h4 [NN*DDIM];
__device__ float g_a1s[NN];
__device__ float g_a1d[NN];
__device__ float g_alpha[EDGES];
__device__ float g_W2T[OUTD*HID];          // [30][512]
__device__ float g_Wfused_r[IN_DIM*HID];   // round_tf32(W_enc @ W1)  [3000,512]
__device__ float g_bfused[HID];            // b_enc @ W1
__device__ float g_Wdec_r[DDIM*IN_DIM];    // [512,3000]
__device__ float g_W1_r  [DDIM*HID];       // [512,512]
__device__ float g_W1T_r [HID*DDIM];       // [512,512] = W1^T

// ---------------- tf32 rounding helpers ----------------
__device__ __forceinline__ float round_tf32f(float x) {
    uint32_t u;
    asm("cvt.rna.tf32.f32 %0, %1;" : "=r"(u) : "f"(x));
    return __uint_as_float(u);
}
__device__ __forceinline__ uint32_t f2tf32(float f) {
    uint32_t u;
    asm("cvt.rna.tf32.f32 %0, %1;" : "=r"(u) : "f"(f));
    return u;
}

// =====================================================================
// TF32 tensor-core GEMM: C[M,N] = A[M,K] @ B[K,N] (+bias)
// CTA 128x128, BK=32, 4 warps (2x2), warp tile 64x64 (CUTLASS shape).
// 3-stage cp.async.cg pipeline, one __syncthreads per k-iteration.
// ACVT: 1 = A raw fp32 -> cvt fragments post-LDS.
// FLAGS bit0 = ELU on output, bit1 = round output to tf32.
// =====================================================================
#define GA_STRIDE 36
#define GB_STRIDE 136
#define STAGES 3
#define STAGE_FLOATS (128*GA_STRIDE + 32*GB_STRIDE)
#define GSMEM_FLOATS (STAGES*STAGE_FLOATS)
#define GSMEM_BYTES  (GSMEM_FLOATS*4)

__device__ __forceinline__ void cp16cg(uint32_t dst, const float* src, int sz) {
    asm volatile("cp.async.cg.shared.global [%0], [%1], 16, %2;\n"
                 :: "r"(dst), "l"(src), "r"(sz));
}

template<int ACVT, int FLAGS>
__global__ __launch_bounds__(128, 2) void tf32_gemm_kernel(
    const float* __restrict__ A, const float* __restrict__ B,
    const float* __restrict__ bias, float* __restrict__ C,
    int M, int N, int K)
{
    extern __shared__ float sm[];
    float* As = sm;                             // [STAGES][128][36]
    float* Bs = sm + STAGES * 128 * GA_STRIDE;  // [STAGES][32][136]

    const int tid  = threadIdx.x;
    const int lane = tid & 31;
    const int warp = tid >> 5;          // 0..3
    const int wm   = warp >> 1;         // 0..1
    const int wn   = warp & 1;          // 0..1
    const int row0 = blockIdx.y * 128;
    const int col0 = blockIdx.x * 128;
    const int lr   = lane >> 2;         // 0..7
    const int lc   = lane & 3;          // 0..3

    float acc[4][8][4];
    #pragma unroll
    for (int i = 0; i < 4; i++)
        #pragma unroll
        for (int j = 0; j < 8; j++)
            #pragma unroll
            for (int q = 0; q < 4; q++) acc[i][j][q] = 0.f;

    const int nk = (K + 31) >> 5;

    auto load_tile = [&](int stage, int kt) {
        const int k0 = kt << 5;
        float* Asb = As + stage * 128 * GA_STRIDE;
        float* Bsb = Bs + stage * 32 * GB_STRIDE;
        #pragma unroll
        for (int it = 0; it < 8; it++) {
            int idx = tid + it * 128;               // 0..1023
            int r = idx >> 3, c4 = (idx & 7) << 2;
            int gr = row0 + r, gc = k0 + c4;
            uint32_t dst = (uint32_t)__cvta_generic_to_shared(&Asb[r * GA_STRIDE + c4]);
            int sz = (gr < M && gc < K) ? 16 : 0;
            cp16cg(dst, A + (size_t)gr * K + gc, sz);
        }
        #pragma unroll
        for (int it = 0; it < 8; it++) {
            int idx = tid + it * 128;
            int r = idx >> 5, c4 = (idx & 31) << 2;
            int gr = k0 + r, gc = col0 + c4;
            uint32_t dst = (uint32_t)__cvta_generic_to_shared(&Bsb[r * GB_STRIDE + c4]);
            int sz = (gr < K && gc < N) ? 16 : 0;
            cp16cg(dst, B + (size_t)gr * N + gc, sz);
        }
    };

    // prologue: 2 prefetches
    load_tile(0, 0);
    asm volatile("cp.async.commit_group;\n");
    if (nk > 1) load_tile(1, 1);
    asm volatile("cp.async.commit_group;\n");

    int stage = 0;
    for (int kt = 0; kt < nk; kt++) {
        asm volatile("cp.async.wait_group 1;\n");
        __syncthreads();

        if (kt + 2 < nk) load_tile((stage + 2 >= STAGES) ? stage + 2 - STAGES : stage + 2, kt + 2);
        asm volatile("cp.async.commit_group;\n");

        const float*    Asf = As + stage * 128 * GA_STRIDE;
        const uint32_t* Asb = (const uint32_t*)Asf;
        const uint32_t* Bsb = (const uint32_t*)(Bs + stage * 32 * GB_STRIDE);

        #pragma unroll
        for (int ks = 0; ks < 4; ks++) {
            const int kk = ks << 3;
            uint32_t a[4][4], b[8][2];
            #pragma unroll
            for (int ti = 0; ti < 4; ti++) {
                int rb = wm * 64 + ti * 16 + lr;
                int kc = kk + lc;
                if (ACVT) {
                    a[ti][0] = f2tf32(Asf[rb * GA_STRIDE + kc]);
                    a[ti][1] = f2tf32(Asf[(rb + 8) * GA_STRIDE + kc]);
                    a[ti][2] = f2tf32(Asf[rb * GA_STRIDE + kc + 4]);
                    a[ti][3] = f2tf32(Asf[(rb + 8) * GA_STRIDE + kc + 4]);
                } else {
                    a[ti][0] = Asb[rb * GA_STRIDE + kc];
                    a[ti][1] = Asb[(rb + 8) * GA_STRIDE + kc];
                    a[ti][2] = Asb[rb * GA_STRIDE + kc + 4];
                    a[ti][3] = Asb[(rb + 8) * GA_STRIDE + kc + 4];
                }
            }
            #pragma unroll
            for (int tj = 0; tj < 8; tj++) {
                int cb = wn * 64 + tj * 8 + lr;
                int kr = kk + lc;
                b[tj][0] = Bsb[kr * GB_STRIDE + cb];
                b[tj][1] = Bsb[(kr + 4) * GB_STRIDE + cb];
            }
            #pragma unroll
            for (int ti = 0; ti < 4; ti++)
                #pragma unroll
                for (int tj = 0; tj < 8; tj++) {
                    asm volatile(
                        "mma.sync.aligned.m16n8k8.row.col.f32.tf32.tf32.f32 "
                        "{%0,%1,%2,%3}, {%4,%5,%6,%7}, {%8,%9}, {%0,%1,%2,%3};\n"
                        : "+f"(acc[ti][tj][0]), "+f"(acc[ti][tj][1]),
                          "+f"(acc[ti][tj][2]), "+f"(acc[ti][tj][3])
                        : "r"(a[ti][0]), "r"(a[ti][1]), "r"(a[ti][2]), "r"(a[ti][3]),
                          "r"(b[tj][0]), "r"(b[tj][1]));
                }
        }
        stage = (stage + 1 >= STAGES) ? 0 : stage + 1;
    }

    // epilogue (float2 stores; c is even)
    constexpr bool DO_ELU   = (FLAGS & 1) != 0;
    constexpr bool DO_ROUND = (FLAGS & 2) != 0;
    #pragma unroll
    for (int ti = 0; ti < 4; ti++) {
        int r0 = row0 + wm * 64 + ti * 16 + lr;
        int r1 = r0 + 8;
        #pragma unroll
        for (int tj = 0; tj < 8; tj++) {
            int c = col0 + wn * 64 + tj * 8 + (lc << 1);
            float bv0 = 0.f, bv1 = 0.f;
            if (bias && c + 1 < N) {
                float2 bv = *(const float2*)(bias + c);
                bv0 = bv.x; bv1 = bv.y;
            } else if (bias && c < N) bv0 = bias[c];
            #pragma unroll
            for (int h = 0; h < 2; h++) {
                int r = h ? r1 : r0;
                if (r >= M) continue;
                float v0 = acc[ti][tj][h*2+0] + bv0;
                float v1 = acc[ti][tj][h*2+1] + bv1;
                if (DO_ELU) {
                    v0 = (v0 > 0.f) ? v0 : expm1f(v0);
                    v1 = (v1 > 0.f) ? v1 : expm1f(v1);
                }
                if (DO_ROUND) { v0 = round_tf32f(v0); v1 = round_tf32f(v1); }
                if (c + 1 < N) {
                    float2 st; st.x = v0; st.y = v1;
                    *(float2*)(C + (size_t)r * N + c) = st;
                } else if (c < N) {
                    C[(size_t)r * N + c] = v0;
                }
            }
        }
    }
}

// ---------------- prep kernels ----------------
__global__ void round_tf32_kernel(const float* __restrict__ in,
                                  float* __restrict__ out, int n)
{
    int i = blockIdx.x * 256 + threadIdx.x;
    if (i >= n) return;
    out[i] = round_tf32f(in[i]);
}

__global__ void transpose_round_kernel(const float* __restrict__ in,
                                       float* __restrict__ out, int R, int C)
{
    __shared__ float t[32][33];
    int c = blockIdx.x * 32 + threadIdx.x;
    int r = blockIdx.y * 32 + threadIdx.y;
    if (r < R && c < C) t[threadIdx.y][threadIdx.x] = in[r * C + c];
    __syncthreads();
    int r2 = blockIdx.x * 32 + threadIdx.y;
    int c2 = blockIdx.y * 32 + threadIdx.x;
    if (r2 < C && c2 < R) out[r2 * R + c2] = round_tf32f(t[threadIdx.x][threadIdx.y]);
}

__global__ void transpose_kernel(const float* __restrict__ in,
                                 float* __restrict__ out, int R, int C)
{
    __shared__ float t[32][33];
    int c = blockIdx.x * 32 + threadIdx.x;
    int r = blockIdx.y * 32 + threadIdx.y;
    if (r < R && c < C) t[threadIdx.y][threadIdx.x] = in[r * C + c];
    __syncthreads();
    int r2 = blockIdx.x * 32 + threadIdx.y;
    int c2 = blockIdx.y * 32 + threadIdx.x;
    if (r2 < C && c2 < R) out[r2 * R + c2] = t[threadIdx.x][threadIdx.y];
}

// bfused[n] = sum_k b_enc[k] * W1[k][n]
__global__ void bias_fuse_kernel(const float* __restrict__ b_enc,
                                 const float* __restrict__ W1,
                                 float* __restrict__ bfused)
{
    int n = blockIdx.x * 128 + threadIdx.x;
    if (n >= HID) return;
    float s = 0.f;
    for (int k = 0; k < DDIM; k++) s += b_enc[k] * W1[(size_t)k * HID + n];
    bfused[n] = s;
}

// ---------------- h2 = h1 @ W2 (N=30), warp-per-row, W2T in smem ----------
#define W2T_SMEM (OUTD*HID*4)
__global__ __launch_bounds__(256) void h2_kernel(
    const float* __restrict__ h1, const float* __restrict__ W2T,
    float* __restrict__ h2)
{
    extern __shared__ float w[];          // [30][512]
    const int tid = threadIdx.x;
    for (int i = tid; i < OUTD * HID; i += 256) w[i] = W2T[i];
    __syncthreads();
    const int wid = tid >> 5, lane = tid & 31;
    const int row = blockIdx.x * 8 + wid;
    if (row >= NN) return;
    float h[16];
    const float* hr = h1 + (size_t)row * HID;
    #pragma unroll
    for (int j = 0; j < 16; j++) h[j] = hr[lane + 32 * j];
    #pragma unroll
    for (int c = 0; c < OUTD; c++) {
        float s = 0.f;
        const float* wc = w + c * HID;
        #pragma unroll
        for (int j = 0; j < 16; j++) s += h[j] * wc[lane + 32 * j];
        #pragma unroll
        for (int o = 16; o > 0; o >>= 1) s += __shfl_xor_sync(0xffffffffu, s, o);
        if (lane == c) h2[(size_t)row * OUTD + c] = s;   // c<30<32
    }
}

// ---------------- x3 = h2 @ W2^T (K=30), warp-per-row, W2T in smem --------
__global__ __launch_bounds__(256) void x3_kernel(
    const float* __restrict__ h2, const float* __restrict__ W2T,
    float* __restrict__ x3)
{
    extern __shared__ float w[];          // [30][512]
    const int tid = threadIdx.x;
    for (int i = tid; i < OUTD * HID; i += 256) w[i] = W2T[i];
    __syncthreads();
    const int wid = tid >> 5, lane = tid & 31;
    const int row = blockIdx.x * 8 + wid;
    if (row >= NN) return;
    float hc = (lane < OUTD) ? h2[(size_t)row * OUTD + lane] : 0.f;
    float acc[16];
    #pragma unroll
    for (int j = 0; j < 16; j++) acc[j] = 0.f;
    #pragma unroll
    for (int c = 0; c < OUTD; c++) {
        float b = __shfl_sync(0xffffffffu, hc, c);
        const float* wc = w + c * HID;
        #pragma unroll
        for (int j = 0; j < 16; j++) acc[j] += b * wc[lane + 32 * j];
    }
    float* xr = x3 + (size_t)row * HID;
    #pragma unroll
    for (int j = 0; j < 16; j++) xr[lane + 32 * j] = acc[j];
}

// ---------------- attention logits ----------------
__global__ void row_logits_kernel(const float* __restrict__ x1,
                                  const float* __restrict__ att_s,
                                  const float* __restrict__ att_d,
                                  float* __restrict__ a1s,
                                  float* __restrict__ a1d, int n)
{
    int row = blockIdx.x * 8 + threadIdx.y;
    if (row >= n) return;
    int lane = threadIdx.x;
    float s = 0.f, d = 0.f;
    const float* xr = x1 + (size_t)row * HID;
    #pragma unroll 4
    for (int k = lane; k < HID; k += 32) {
        float v = xr[k];
        s += v * att_s[k];
        d += v * att_d[k];
    }
    #pragma unroll
    for (int o = 16; o > 0; o >>= 1) {
        s += __shfl_down_sync(0xffffffffu, s, o);
        d += __shfl_down_sync(0xffffffffu, d, o);
    }
    if (lane == 0) { a1s[row] = s; a1d[row] = d; }
}

// ---------------- edge softmax ----------------
__global__ void alpha_kernel(const int* __restrict__ src,
                             const int* __restrict__ dst,
                             const float* __restrict__ a1s,
                             const float* __restrict__ a1d,
                             float* __restrict__ alpha, int n)
{
    int i = blockIdx.x * 256 + threadIdx.x;
    if (i >= n) return;
    float e[DEG];
    float m = -1e30f;
    #pragma unroll
    for (int j = 0; j < DEG; j++) {
        int eidx = i * DEG + j;
        float v = a1s[src[eidx]] + a1d[dst[eidx]];
        v = (v > 0.f) ? v : NEG_SLOPE * v;
        e[j] = v;
        m = fmaxf(m, v);
    }
    float sum = 0.f;
    #pragma unroll
    for (int j = 0; j < DEG; j++) { e[j] = __expf(e[j] - m); sum += e[j]; }
    float inv = 1.f / sum;
    #pragma unroll
    for (int j = 0; j < DEG; j++) alpha[i * DEG + j] = e[j] * inv;
}

// ---------------- weighted aggregation + ELU (+opt round) ----------------
__global__ __launch_bounds__(128) void agg_elu_kernel(
    const float* __restrict__ x, const int* __restrict__ src,
    const float* __restrict__ alpha, float* __restrict__ out, int round_out)
{
    int i = blockIdx.x;
    __shared__ int   ss[DEG];
    __shared__ float sa[DEG];
    if (threadIdx.x < DEG) {
        ss[threadIdx.x] = src[i * DEG + threadIdx.x];
        sa[threadIdx.x] = alpha[i * DEG + threadIdx.x];
    }
    __syncthreads();
    int c0 = threadIdx.x * 4;
    float a0 = 0.f, a1 = 0.f, a2 = 0.f, a3 = 0.f;
    #pragma unroll
    for (int j = 0; j < DEG; j++) {
        const float4 v = *(const float4*)&x[(size_t)ss[j] * HID + c0];
        float a = sa[j];
        a0 += a * v.x; a1 += a * v.y; a2 += a * v.z; a3 += a * v.w;
    }
    float4 r;
    r.x = (a0 > 0.f) ? a0 : expm1f(a0);
    r.y = (a1 > 0.f) ? a1 : expm1f(a1);
    r.z = (a2 > 0.f) ? a2 : expm1f(a2);
    r.w = (a3 > 0.f) ? a3 : expm1f(a3);
    if (round_out) {
        r.x = round_tf32f(r.x); r.y = round_tf32f(r.y);
        r.z = round_tf32f(r.z); r.w = round_tf32f(r.w);
    }
    *(float4*)&out[(size_t)i * HID + c0] = r;
}

// ---------------- prediction head ----------------
__global__ void pred_kernel(const float* __restrict__ h2,
                            const float* __restrict__ Wp,
                            const float* __restrict__ bp,
                            float* __restrict__ logp, int n)
{
    int i = blockIdx.x * 128 + threadIdx.x;
    if (i >= n) return;
    float h[OUTD];
    #pragma unroll
    for (int k = 0; k < OUTD; k++) h[k] = h2[(size_t)i * OUTD + k];
    float p[PREDD];
    float m = -1e30f;
    #pragma unroll
    for (int c = 0; c < PREDD; c++) {
        float s = bp[c];
        #pragma unroll
        for (int k = 0; k < OUTD; k++) s += h[k] * Wp[k * PREDD + c];
        p[c] = s;
        m = fmaxf(m, s);
    }
    float sum = 0.f;
    #pragma unroll
    for (int c = 0; c < PREDD; c++) sum += expf(p[c] - m);
    float lse = m + logf(sum);
    #pragma unroll
    for (int c = 0; c < PREDD; c++) logp[(size_t)i * PREDD + c] = p[c] - lse;
}

// ---------------- launch ----------------
static inline dim3 tf32_grid(int M, int N) {
    return dim3((N + 127) / 128, (M + 127) / 128);
}

extern "C" void kernel_launch(void* const* d_in, const int* in_sizes, int n_in,
                              void* d_out, int out_size)
{
    const float* features = (const float*)d_in[0];
    const int*   edge     = (const int*)  d_in[1];
    const float* W_enc    = (const float*)d_in[2];
    const float* b_enc    = (const float*)d_in[3];
    const float* W1       = (const float*)d_in[4];
    const float* att_src  = (const float*)d_in[5];
    const float* att_dst  = (const float*)d_in[6];
    const float* W2       = (const float*)d_in[7];
    const float* W_pred   = (const float*)d_in[8];
    const float* b_pred   = (const float*)d_in[9];
    const float* W_dec    = (const float*)d_in[10];
    const float* b_dec    = (const float*)d_in[11];

    const int* src = edge;
    const int* dst = edge + EDGES;

    float* out  = (float*)d_out;
    float* h2   = out;
    float* outm = out + (size_t)NN * OUTD;
    float* logp = out + (size_t)NN * OUTD + (size_t)NN * IN_DIM;

    float *x1, *h1, *x3, *h3, *h4, *a1s, *a1d, *alpha, *W2T;
    float *Wfused_r, *bfused, *Wdec_r, *W1_r, *W1T_r;
    cudaGetSymbolAddress((void**)&x1,    g_x1);
    cudaGetSymbolAddress((void**)&h1,    g_h1);
    cudaGetSymbolAddress((void**)&x3,    g_x3);
    cudaGetSymbolAddress((void**)&h3,    g_h3);
    cudaGetSymbolAddress((void**)&h4,    g_h4);
    cudaGetSymbolAddress((void**)&a1s,   g_a1s);
    cudaGetSymbolAddress((void**)&a1d,   g_a1d);
    cudaGetSymbolAddress((void**)&alpha, g_alpha);
    cudaGetSymbolAddress((void**)&W2T,   g_W2T);
    cudaGetSymbolAddress((void**)&Wfused_r, g_Wfused_r);
    cudaGetSymbolAddress((void**)&bfused,   g_bfused);
    cudaGetSymbolAddress((void**)&Wdec_r,   g_Wdec_r);
    cudaGetSymbolAddress((void**)&W1_r,     g_W1_r);
    cudaGetSymbolAddress((void**)&W1T_r,    g_W1T_r);

    static int attr_set = 0;
    if (!attr_set) {
        cudaFuncSetAttribute(tf32_gemm_kernel<1,2>,
            cudaFuncAttributeMaxDynamicSharedMemorySize, GSMEM_BYTES);
        cudaFuncSetAttribute(tf32_gemm_kernel<1,0>,
            cudaFuncAttributeMaxDynamicSharedMemorySize, GSMEM_BYTES);
        cudaFuncSetAttribute(tf32_gemm_kernel<0,0>,
            cudaFuncAttributeMaxDynamicSharedMemorySize, GSMEM_BYTES);
        cudaFuncSetAttribute(tf32_gemm_kernel<0,3>,
            cudaFuncAttributeMaxDynamicSharedMemorySize, GSMEM_BYTES);
        cudaFuncSetAttribute(h2_kernel,
            cudaFuncAttributeMaxDynamicSharedMemorySize, W2T_SMEM);
        cudaFuncSetAttribute(x3_kernel,
            cudaFuncAttributeMaxDynamicSharedMemorySize, W2T_SMEM);
        attr_set = 1;
    }

    // ---- weight prep ----
    round_tf32_kernel<<<(DDIM*IN_DIM + 255)/256, 256>>>(W_dec, Wdec_r, DDIM*IN_DIM);
    round_tf32_kernel<<<(DDIM*HID + 255)/256, 256>>>(W1, W1_r, DDIM*HID);
    transpose_round_kernel<<<dim3((HID + 31)/32, (DDIM + 31)/32), dim3(32, 32)>>>(W1, W1T_r, DDIM, HID);
    transpose_kernel<<<dim3((OUTD + 31)/32, (HID + 31)/32), dim3(32, 32)>>>(W2, W2T, HID, OUTD);
    bias_fuse_kernel<<<(HID + 127)/128, 128>>>(b_enc, W1, bfused);
    // Wfused = round_tf32(W_enc @ W1)   [3000,512] K=512
    tf32_gemm_kernel<1,2><<<tf32_grid(IN_DIM, HID), 128, GSMEM_BYTES>>>(
        W_enc, W1_r, nullptr, Wfused_r, IN_DIM, HID, DDIM);

    // 1. x1 = features @ Wfused + bfused    [30000,512] K=3000 (enc+x1 fused)
    tf32_gemm_kernel<1,0><<<tf32_grid(NN, HID), 128, GSMEM_BYTES>>>(
        features, Wfused_r, bfused, x1, NN, HID, IN_DIM);
    // 2. attention logits
    row_logits_kernel<<<(NN + 7)/8, dim3(32, 8)>>>(x1, att_src, att_dst, a1s, a1d, NN);
    // 3. edge softmax
    alpha_kernel<<<(NN + 255)/256, 256>>>(src, dst, a1s, a1d, alpha, NN);
    // 4. h1 = elu(agg(x1))
    agg_elu_kernel<<<NN, 128>>>(x1, src, alpha, h1, 0);
    // 5. h2 = h1 @ W2  (output 0)
    h2_kernel<<<(NN + 7)/8, 256, W2T_SMEM>>>(h1, W2T, h2);
    // 6. log-softmax head (output 2)
    pred_kernel<<<(NN + 127)/128, 128>>>(h2, W_pred, b_pred, logp, NN);
    // 7. x3 = h2 @ W2^T
    x3_kernel<<<(NN + 7)/8, 256, W2T_SMEM>>>(h2, W2T, x3);
    // 8. h3 = round_tf32(elu(agg(x3)))
    agg_elu_kernel<<<NN, 128>>>(x3, src, alpha, h3, 1);
    // 9. h4 = round_tf32(elu(h3 @ W1^T))     [30000,512] K=512
    tf32_gemm_kernel<0,3><<<tf32_grid(NN, DDIM), 128, GSMEM_BYTES>>>(
        h3, W1T_r, nullptr, h4, NN, DDIM, HID);
    // 10. out = h4 @ W_dec + b_dec           [30000,3000] K=512 (output 1)
    tf32_gemm_kernel<0,0><<<tf32_grid(NN, IN_DIM), 128, GSMEM_BYTES>>>(
        h4, Wdec_r, b_dec, outm, NN, IN_DIM, DDIM);
}

// round 10
// speedup vs baseline: 1.2931x; 1.0063x over previous
#include <cuda_runtime.h>
#include <cuda_bf16.h>
#include <math.h>
#include <stdint.h>

// ---------------- problem constants ----------------
#define NN      30000
#define IN_DIM  3000
#define DDIM    512
#define HID     512
#define OUTD    30
#define PREDD   20
#define DEG     10
#define EDGES   (NN*DEG)
#define NEG_SLOPE 0.2f

// ---------------- scratch ----------------
__device__ float g_x1 [NN*HID];
__device__ float g_h1 [NN*HID];
__device__ float g_x3 [NN*HID];
__device__ float g_h3 [NN*HID];
__device__ float g_h4 [NN*DDIM];
__device__ float g_a1s[NN];
__device__ float g_a1d[NN];
__device__ float g_alpha[EDGES];
__device__ float g_W2T[OUTD*HID];            // [30][512]
__device__ float g_bfused[HID];              // b_enc @ W1
__device__ float g_Wfused_r[IN_DIM*HID];     // round_tf32(W_enc @ W1), row-major
// fragment-permuted padded B operands: [NB][KB][4096]
__device__ float g_W1_p    [16*4 *4096];     // W1      K=512  N=512
__device__ float g_W1T_p   [16*4 *4096];     // W1^T    K=512  N=512
__device__ float g_Wdec_p  [16*24*4096];     // W_dec   K=512  N=3000(->3072)
__device__ float g_Wfused_p[94*4 *4096];     // Wfused  K=3000(->3008) N=512

// ---------------- tf32 rounding helpers ----------------
__device__ __forceinline__ float round_tf32f(float x) {
    uint32_t u;
    asm("cvt.rna.tf32.f32 %0, %1;" : "=r"(u) : "f"(x));
    return __uint_as_float(u);
}
__device__ __forceinline__ uint32_t f2tf32(float f) {
    uint32_t u;
    asm("cvt.rna.tf32.f32 %0, %1;" : "=r"(u) : "f"(f));
    return u;
}

// =====================================================================
// TF32 tensor-core GEMM: C[M,N] = A[M,K] @ B (+bias)
// B is PRE-PERMUTED into mma fragment order (padded, no bounds checks):
//   tile (nb, kt) is a contiguous 4096-float block:
//   offset = ks*1024 + tjj*64 + lane*2 + part, value = B[kt*32+ks*8+part*4+(lane&3)]
//                                                      [nb*128+tjj*8+(lane>>2)]
// CTA 128x128, BK=32, 4 warps (2x2), warp tile 64x64.
// 3-stage cp.async.cg pipeline, one __syncthreads per k-iteration.
// ACVT: 1 = A raw fp32 -> cvt fragments post-LDS.
// FLAGS bit0 = ELU on output, bit1 = round output to tf32.
// =====================================================================
#define GA_STRIDE 36
#define BSTAGE 4096
#define STAGES 3
#define STAGE_FLOATS (128*GA_STRIDE + BSTAGE)
#define GSMEM_BYTES  (STAGES*STAGE_FLOATS*4)

__device__ __forceinline__ void cp16cg(uint32_t dst, const float* src, int sz) {
    asm volatile("cp.async.cg.shared.global [%0], [%1], 16, %2;\n"
                 :: "r"(dst), "l"(src), "r"(sz));
}

template<int ACVT, int FLAGS>
__global__ __launch_bounds__(128, 2) void tf32_gemm_kernel(
    const float* __restrict__ A, const float* __restrict__ Bp,
    const float* __restrict__ bias, float* __restrict__ C,
    int M, int N, int K, int KB)
{
    extern __shared__ float sm[];
    float* As = sm;                             // [STAGES][128][36]
    float* Bs = sm + STAGES * 128 * GA_STRIDE;  // [STAGES][4096]

    const int tid  = threadIdx.x;
    const int lane = tid & 31;
    const int warp = tid >> 5;          // 0..3
    const int wm   = warp >> 1;         // 0..1
    const int wn   = warp & 1;          // 0..1
    const int row0 = blockIdx.y * 128;
    const int col0 = blockIdx.x * 128;
    const int lr   = lane >> 2;         // 0..7
    const int lc   = lane & 3;          // 0..3

    float acc[4][8][4];
    #pragma unroll
    for (int i = 0; i < 4; i++)
        #pragma unroll
        for (int j = 0; j < 8; j++)
            #pragma unroll
            for (int q = 0; q < 4; q++) acc[i][j][q] = 0.f;

    const int nk = KB;
    const float* Btiles = Bp + (size_t)blockIdx.x * KB * BSTAGE;

    auto load_tile = [&](int stage, int kt) {
        const int k0 = kt << 5;
        float* Asb = As + stage * 128 * GA_STRIDE;
        float* Bsb = Bs + stage * BSTAGE;
        #pragma unroll
        for (int it = 0; it < 8; it++) {
            int idx = tid + it * 128;               // 0..1023
            int r = idx >> 3, c4 = (idx & 7) << 2;
            int gr = row0 + r, gc = k0 + c4;
            uint32_t dst = (uint32_t)__cvta_generic_to_shared(&Asb[r * GA_STRIDE + c4]);
            int sz = (gr < M && gc < K) ? 16 : 0;
            cp16cg(dst, A + (size_t)gr * K + gc, sz);
        }
        const float* Bt = Btiles + (size_t)kt * BSTAGE;
        #pragma unroll
        for (int it = 0; it < 8; it++) {
            int c4 = (tid + it * 128) << 2;         // float offset, 16B chunks
            uint32_t dst = (uint32_t)__cvta_generic_to_shared(&Bsb[c4]);
            cp16cg(dst, Bt + c4, 16);
        }
    };

    // prologue: 2 prefetches
    load_tile(0, 0);
    asm volatile("cp.async.commit_group;\n");
    if (nk > 1) load_tile(1, 1);
    asm volatile("cp.async.commit_group;\n");

    int stage = 0;
    for (int kt = 0; kt < nk; kt++) {
        asm volatile("cp.async.wait_group 1;\n");
        __syncthreads();

        if (kt + 2 < nk) load_tile((stage + 2 >= STAGES) ? stage + 2 - STAGES : stage + 2, kt + 2);
        asm volatile("cp.async.commit_group;\n");

        const float*    Asf = As + stage * 128 * GA_STRIDE;
        const uint32_t* Asb = (const uint32_t*)Asf;
        const float*    Bsb = Bs + stage * BSTAGE;

        #pragma unroll
        for (int ks = 0; ks < 4; ks++) {
            const int kk = ks << 3;
            uint32_t a[4][4];
            uint2 b[8];
            #pragma unroll
            for (int ti = 0; ti < 4; ti++) {
                int rb = wm * 64 + ti * 16 + lr;
                int kc = kk + lc;
                if (ACVT) {
                    a[ti][0] = f2tf32(Asf[rb * GA_STRIDE + kc]);
                    a[ti][1] = f2tf32(Asf[(rb + 8) * GA_STRIDE + kc]);
                    a[ti][2] = f2tf32(Asf[rb * GA_STRIDE + kc + 4]);
                    a[ti][3] = f2tf32(Asf[(rb + 8) * GA_STRIDE + kc + 4]);
                } else {
                    a[ti][0] = Asb[rb * GA_STRIDE + kc];
                    a[ti][1] = Asb[(rb + 8) * GA_STRIDE + kc];
                    a[ti][2] = Asb[rb * GA_STRIDE + kc + 4];
                    a[ti][3] = Asb[(rb + 8) * GA_STRIDE + kc + 4];
                }
            }
            #pragma unroll
            for (int tj = 0; tj < 8; tj++) {
                int tjj = wn * 8 + tj;
                b[tj] = *(const uint2*)(Bsb + (ks << 10) + (tjj << 6) + (lane << 1));
            }
            #pragma unroll
            for (int ti = 0; ti < 4; ti++)
                #pragma unroll
                for (int tj = 0; tj < 8; tj++) {
                    asm volatile(
                        "mma.sync.aligned.m16n8k8.row.col.f32.tf32.tf32.f32 "
                        "{%0,%1,%2,%3}, {%4,%5,%6,%7}, {%8,%9}, {%0,%1,%2,%3};\n"
                        : "+f"(acc[ti][tj][0]), "+f"(acc[ti][tj][1]),
                          "+f"(acc[ti][tj][2]), "+f"(acc[ti][tj][3])
                        : "r"(a[ti][0]), "r"(a[ti][1]), "r"(a[ti][2]), "r"(a[ti][3]),
                          "r"(b[tj].x), "r"(b[tj].y));
                }
        }
        stage = (stage + 1 >= STAGES) ? 0 : stage + 1;
    }

    // epilogue (float2 stores; c is even)
    constexpr bool DO_ELU   = (FLAGS & 1) != 0;
    constexpr bool DO_ROUND = (FLAGS & 2) != 0;
    #pragma unroll
    for (int ti = 0; ti < 4; ti++) {
        int r0 = row0 + wm * 64 + ti * 16 + lr;
        int r1 = r0 + 8;
        #pragma unroll
        for (int tj = 0; tj < 8; tj++) {
            int c = col0 + wn * 64 + tj * 8 + (lc << 1);
            float bv0 = 0.f, bv1 = 0.f;
            if (bias && c + 1 < N) {
                float2 bv = *(const float2*)(bias + c);
                bv0 = bv.x; bv1 = bv.y;
            } else if (bias && c < N) bv0 = bias[c];
            #pragma unroll
            for (int h = 0; h < 2; h++) {
                int r = h ? r1 : r0;
                if (r >= M) continue;
                float v0 = acc[ti][tj][h*2+0] + bv0;
                float v1 = acc[ti][tj][h*2+1] + bv1;
                if (DO_ELU) {
                    v0 = (v0 > 0.f) ? v0 : expm1f(v0);
                    v1 = (v1 > 0.f) ? v1 : expm1f(v1);
                }
                if (DO_ROUND) { v0 = round_tf32f(v0); v1 = round_tf32f(v1); }
                if (c + 1 < N) {
                    float2 st; st.x = v0; st.y = v1;
                    *(float2*)(C + (size_t)r * N + c) = st;
                } else if (c < N) {
                    C[(size_t)r * N + c] = v0;
                }
            }
        }
    }
}

// ---------------- B permutation prep ----------------
// dst[nb][kt][ks*1024 + tjj*64 + lane*2 + part] =
//   src(k = kt*32+ks*8+part*4+(lane&3), n = nb*128+tjj*8+(lane>>2))  (0 if OOB)
__global__ void perm_b_kernel(const float* __restrict__ src, float* __restrict__ dst,
                              int K, int N, int KB, int NB, int ld,
                              int trans, int do_round)
{
    int i = blockIdx.x * 256 + threadIdx.x;
    int total = KB * NB * 4096;
    if (i >= total) return;
    int tile = i >> 12, off = i & 4095;
    int kt = tile % KB, nb = tile / KB;
    int ks = off >> 10, rem = off & 1023;
    int tjj = rem >> 6, r2 = rem & 63;
    int lane = r2 >> 1, part = r2 & 1;
    int k = kt * 32 + ks * 8 + part * 4 + (lane & 3);
    int n = nb * 128 + tjj * 8 + (lane >> 2);
    float v = 0.f;
    if (k < K && n < N)
        v = trans ? src[(size_t)n * ld + k] : src[(size_t)k * ld + n];
    if (do_round) v = round_tf32f(v);
    dst[i] = v;
}

// ---------------- other prep ----------------
__global__ void transpose_kernel(const float* __restrict__ in,
                                 float* __restrict__ out, int R, int C)
{
    __shared__ float t[32][33];
    int c = blockIdx.x * 32 + threadIdx.x;
    int r = blockIdx.y * 32 + threadIdx.y;
    if (r < R && c < C) t[threadIdx.y][threadIdx.x] = in[r * C + c];
    __syncthreads();
    int r2 = blockIdx.x * 32 + threadIdx.y;
    int c2 = blockIdx.y * 32 + threadIdx.x;
    if (r2 < C && c2 < R) out[r2 * R + c2] = t[threadIdx.x][threadIdx.y];
}

// bfused[n] = sum_k b_enc[k] * W1[k][n]
__global__ void bias_fuse_kernel(const float* __restrict__ b_enc,
                                 const float* __restrict__ W1,
                                 float* __restrict__ bfused)
{
    int n = blockIdx.x * 128 + threadIdx.x;
    if (n >= HID) return;
    float s = 0.f;
    for (int k = 0; k < DDIM; k++) s += b_enc[k] * W1[(size_t)k * HID + n];
    bfused[n] = s;
}

// ---------------- h2 = h1 @ W2 (N=30), warp-per-row, W2T in smem ----------
#define W2T_SMEM (OUTD*HID*4)
__global__ __launch_bounds__(256) void h2_kernel(
    const float* __restrict__ h1, const float* __restrict__ W2T,
    float* __restrict__ h2)
{
    extern __shared__ float w[];          // [30][512]
    const int tid = threadIdx.x;
    for (int i = tid; i < OUTD * HID; i += 256) w[i] = W2T[i];
    __syncthreads();
    const int wid = tid >> 5, lane = tid & 31;
    const int row = blockIdx.x * 8 + wid;
    if (row >= NN) return;
    float h[16];
    const float* hr = h1 + (size_t)row * HID;
    #pragma unroll
    for (int j = 0; j < 16; j++) h[j] = hr[lane + 32 * j];
    #pragma unroll
    for (int c = 0; c < OUTD; c++) {
        float s = 0.f;
        const float* wc = w + c * HID;
        #pragma unroll
        for (int j = 0; j < 16; j++) s += h[j] * wc[lane + 32 * j];
        #pragma unroll
        for (int o = 16; o > 0; o >>= 1) s += __shfl_xor_sync(0xffffffffu, s, o);
        if (lane == c) h2[(size_t)row * OUTD + c] = s;   // c<30<32
    }
}

// ---------------- x3 = h2 @ W2^T (K=30), warp-per-row, W2T in smem --------
__global__ __launch_bounds__(256) void x3_kernel(
    const float* __restrict__ h2, const float* __restrict__ W2T,
    float* __restrict__ x3)
{
    extern __shared__ float w[];          // [30][512]
    const int tid = threadIdx.x;
    for (int i = tid; i < OUTD * HID; i += 256) w[i] = W2T[i];
    __syncthreads();
    const int wid = tid >> 5, lane = tid & 31;
    const int row = blockIdx.x * 8 + wid;
    if (row >= NN) return;
    float hc = (lane < OUTD) ? h2[(size_t)row * OUTD + lane] : 0.f;
    float acc[16];
    #pragma unroll
    for (int j = 0; j < 16; j++) acc[j] = 0.f;
    #pragma unroll
    for (int c = 0; c < OUTD; c++) {
        float b = __shfl_sync(0xffffffffu, hc, c);
        const float* wc = w + c * HID;
        #pragma unroll
        for (int j = 0; j < 16; j++) acc[j] += b * wc[lane + 32 * j];
    }
    float* xr = x3 + (size_t)row * HID;
    #pragma unroll
    for (int j = 0; j < 16; j++) xr[lane + 32 * j] = acc[j];
}

// ---------------- attention logits ----------------
__global__ void row_logits_kernel(const float* __restrict__ x1,
                                  const float* __restrict__ att_s,
                                  const float* __restrict__ att_d,
                                  float* __restrict__ a1s,
                                  float* __restrict__ a1d, int n)
{
    int row = blockIdx.x * 8 + threadIdx.y;
    if (row >= n) return;
    int lane = threadIdx.x;
    float s = 0.f, d = 0.f;
    const float* xr = x1 + (size_t)row * HID;
    #pragma unroll 4
    for (int k = lane; k < HID; k += 32) {
        float v = xr[k];
        s += v * att_s[k];
        d += v * att_d[k];
    }
    #pragma unroll
    for (int o = 16; o > 0; o >>= 1) {
        s += __shfl_down_sync(0xffffffffu, s, o);
        d += __shfl_down_sync(0xffffffffu, d, o);
    }
    if (lane == 0) { a1s[row] = s; a1d[row] = d; }
}

// ---------------- edge softmax ----------------
__global__ void alpha_kernel(const int* __restrict__ src,
                             const int* __restrict__ dst,
                             const float* __restrict__ a1s,
                             const float* __restrict__ a1d,
                             float* __restrict__ alpha, int n)
{
    int i = blockIdx.x * 256 + threadIdx.x;
    if (i >= n) return;
    float e[DEG];
    float m = -1e30f;
    #pragma unroll
    for (int j = 0; j < DEG; j++) {
        int eidx = i * DEG + j;
        float v = a1s[src[eidx]] + a1d[dst[eidx]];
        v = (v > 0.f) ? v : NEG_SLOPE * v;
        e[j] = v;
        m = fmaxf(m, v);
    }
    float sum = 0.f;
    #pragma unroll
    for (int j = 0; j < DEG; j++) { e[j] = __expf(e[j] - m); sum += e[j]; }
    float inv = 1.f / sum;
    #pragma unroll
    for (int j = 0; j < DEG; j++) alpha[i * DEG + j] = e[j] * inv;
}

// ---------------- weighted aggregation + ELU (+opt round) ----------------
__global__ __launch_bounds__(128) void agg_elu_kernel(
    const float* __restrict__ x, const int* __restrict__ src,
    const float* __restrict__ alpha, float* __restrict__ out, int round_out)
{
    int i = blockIdx.x;
    __shared__ int   ss[DEG];
    __shared__ float sa[DEG];
    if (threadIdx.x < DEG) {
        ss[threadIdx.x] = src[i * DEG + threadIdx.x];
        sa[threadIdx.x] = alpha[i * DEG + threadIdx.x];
    }
    __syncthreads();
    int c0 = threadIdx.x * 4;
    float a0 = 0.f, a1 = 0.f, a2 = 0.f, a3 = 0.f;
    #pragma unroll
    for (int j = 0; j < DEG; j++) {
        const float4 v = *(const float4*)&x[(size_t)ss[j] * HID + c0];
        float a = sa[j];
        a0 += a * v.x; a1 += a * v.y; a2 += a * v.z; a3 += a * v.w;
    }
    float4 r;
    r.x = (a0 > 0.f) ? a0 : expm1f(a0);
    r.y = (a1 > 0.f) ? a1 : expm1f(a1);
    r.z = (a2 > 0.f) ? a2 : expm1f(a2);
    r.w = (a3 > 0.f) ? a3 : expm1f(a3);
    if (round_out) {
        r.x = round_tf32f(r.x); r.y = round_tf32f(r.y);
        r.z = round_tf32f(r.z); r.w = round_tf32f(r.w);
    }
    *(float4*)&out[(size_t)i * HID + c0] = r;
}

// ---------------- prediction head ----------------
__global__ void pred_kernel(const float* __restrict__ h2,
                            const float* __restrict__ Wp,
                            const float* __restrict__ bp,
                            float* __restrict__ logp, int n)
{
    int i = blockIdx.x * 128 + threadIdx.x;
    if (i >= n) return;
    float h[OUTD];
    #pragma unroll
    for (int k = 0; k < OUTD; k++) h[k] = h2[(size_t)i * OUTD + k];
    float p[PREDD];
    float m = -1e30f;
    #pragma unroll
    for (int c = 0; c < PREDD; c++) {
        float s = bp[c];
        #pragma unroll
        for (int k = 0; k < OUTD; k++) s += h[k] * Wp[k * PREDD + c];
        p[c] = s;
        m = fmaxf(m, s);
    }
    float sum = 0.f;
    #pragma unroll
    for (int c = 0; c < PREDD; c++) sum += expf(p[c] - m);
    float lse = m + logf(sum);
    #pragma unroll
    for (int c = 0; c < PREDD; c++) logp[(size_t)i * PREDD + c] = p[c] - lse;
}

// ---------------- launch ----------------
static inline dim3 tf32_grid(int M, int N) {
    return dim3((N + 127) / 128, (M + 127) / 128);
}

extern "C" void kernel_launch(void* const* d_in, const int* in_sizes, int n_in,
                              void* d_out, int out_size)
{
    const float* features = (const float*)d_in[0];
    const int*   edge     = (const int*)  d_in[1];
    const float* W_enc    = (const float*)d_in[2];
    const float* b_enc    = (const float*)d_in[3];
    const float* W1       = (const float*)d_in[4];
    const float* att_src  = (const float*)d_in[5];
    const float* att_dst  = (const float*)d_in[6];
    const float* W2       = (const float*)d_in[7];
    const float* W_pred   = (const float*)d_in[8];
    const float* b_pred   = (const float*)d_in[9];
    const float* W_dec    = (const float*)d_in[10];
    const float* b_dec    = (const float*)d_in[11];

    const int* src = edge;
    const int* dst = edge + EDGES;

    float* out  = (float*)d_out;
    float* h2   = out;
    float* outm = out + (size_t)NN * OUTD;
    float* logp = out + (size_t)NN * OUTD + (size_t)NN * IN_DIM;

    float *x1, *h1, *x3, *h3, *h4, *a1s, *a1d, *alpha, *W2T;
    float *bfused, *Wfused_r, *W1_p, *W1T_p, *Wdec_p, *Wfused_p;
    cudaGetSymbolAddress((void**)&x1,    g_x1);
    cudaGetSymbolAddress((void**)&h1,    g_h1);
    cudaGetSymbolAddress((void**)&x3,    g_x3);
    cudaGetSymbolAddress((void**)&h3,    g_h3);
    cudaGetSymbolAddress((void**)&h4,    g_h4);
    cudaGetSymbolAddress((void**)&a1s,   g_a1s);
    cudaGetSymbolAddress((void**)&a1d,   g_a1d);
    cudaGetSymbolAddress((void**)&alpha, g_alpha);
    cudaGetSymbolAddress((void**)&W2T,   g_W2T);
    cudaGetSymbolAddress((void**)&bfused,   g_bfused);
    cudaGetSymbolAddress((void**)&Wfused_r, g_Wfused_r);
    cudaGetSymbolAddress((void**)&W1_p,     g_W1_p);
    cudaGetSymbolAddress((void**)&W1T_p,    g_W1T_p);
    cudaGetSymbolAddress((void**)&Wdec_p,   g_Wdec_p);
    cudaGetSymbolAddress((void**)&Wfused_p, g_Wfused_p);

    static int attr_set = 0;
    if (!attr_set) {
        cudaFuncSetAttribute(tf32_gemm_kernel<1,2>,
            cudaFuncAttributeMaxDynamicSharedMemorySize, GSMEM_BYTES);
        cudaFuncSetAttribute(tf32_gemm_kernel<1,0>,
            cudaFuncAttributeMaxDynamicSharedMemorySize, GSMEM_BYTES);
        cudaFuncSetAttribute(tf32_gemm_kernel<0,0>,
            cudaFuncAttributeMaxDynamicSharedMemorySize, GSMEM_BYTES);
        cudaFuncSetAttribute(tf32_gemm_kernel<0,3>,
            cudaFuncAttributeMaxDynamicSharedMemorySize, GSMEM_BYTES);
        cudaFuncSetAttribute(h2_kernel,
            cudaFuncAttributeMaxDynamicSharedMemorySize, W2T_SMEM);
        cudaFuncSetAttribute(x3_kernel,
            cudaFuncAttributeMaxDynamicSharedMemorySize, W2T_SMEM);
        attr_set = 1;
    }

    // ---- weight prep ----
    // permuted W1 (B of the Wfused GEMM): K=512, N=512, round
    perm_b_kernel<<<(16*4*4096 + 255)/256, 256>>>(W1, W1_p, DDIM, HID, 16, 4, HID, 0, 1);
    // permuted W1^T (B of h4 GEMM): B[k][n] = W1[n][k]
    perm_b_kernel<<<(16*4*4096 + 255)/256, 256>>>(W1, W1T_p, HID, DDIM, 16, 4, HID, 1, 1);
    // permuted W_dec (B of dec GEMM): K=512, N=3000
    perm_b_kernel<<<(16*24*4096 + 255)/256, 256>>>(W_dec, Wdec_p, DDIM, IN_DIM, 16, 24, IN_DIM, 0, 1);
    transpose_kernel<<<dim3((OUTD + 31)/32, (HID + 31)/32), dim3(32, 32)>>>(W2, W2T, HID, OUTD);
    bias_fuse_kernel<<<(HID + 127)/128, 128>>>(b_enc, W1, bfused);
    // Wfused = round_tf32(W_enc @ W1)   [3000,512], then permute (K=3000, N=512)
    tf32_gemm_kernel<1,2><<<tf32_grid(IN_DIM, HID), 128, GSMEM_BYTES>>>(
        W_enc, W1_p, nullptr, Wfused_r, IN_DIM, HID, DDIM, 16);
    perm_b_kernel<<<(94*4*4096 + 255)/256, 256>>>(Wfused_r, Wfused_p, IN_DIM, HID, 94, 4, HID, 0, 0);

    // 1. x1 = features @ Wfused + bfused    [30000,512] K=3000 (enc+x1 fused)
    tf32_gemm_kernel<1,0><<<tf32_grid(NN, HID), 128, GSMEM_BYTES>>>(
        features, Wfused_p, bfused, x1, NN, HID, IN_DIM, 94);
    // 2. attention logits
    row_logits_kernel<<<(NN + 7)/8, dim3(32, 8)>>>(x1, att_src, att_dst, a1s, a1d, NN);
    // 3. edge softmax
    alpha_kernel<<<(NN + 255)/256, 256>>>(src, dst, a1s, a1d, alpha, NN);
    // 4. h1 = elu(agg(x1))
    agg_elu_kernel<<<NN, 128>>>(x1, src, alpha, h1, 0);
    // 5. h2 = h1 @ W2  (output 0)
    h2_kernel<<<(NN + 7)/8, 256, W2T_SMEM>>>(h1, W2T, h2);
    // 6. log-softmax head (output 2)
    pred_kernel<<<(NN + 127)/128, 128>>>(h2, W_pred, b_pred, logp, NN);
    // 7. x3 = h2 @ W2^T
    x3_kernel<<<(NN + 7)/8, 256, W2T_SMEM>>>(h2, W2T, x3);
    // 8. h3 = round_tf32(elu(agg(x3)))
    agg_elu_kernel<<<NN, 128>>>(x3, src, alpha, h3, 1);
    // 9. h4 = round_tf32(elu(h3 @ W1^T))     [30000,512] K=512
    tf32_gemm_kernel<0,3><<<tf32_grid(NN, DDIM), 128, GSMEM_BYTES>>>(
        h3, W1T_p, nullptr, h4, NN, DDIM, HID, 16);
    // 10. out = h4 @ W_dec + b_dec           [30000,3000] K=512 (output 1)
    tf32_gemm_kernel<0,0><<<tf32_grid(NN, IN_DIM), 128, GSMEM_BYTES>>>(
        h4, Wdec_p, b_dec, outm, NN, IN_DIM, DDIM, 16);
}